// round 6
// baseline (speedup 1.0000x reference)
#include <cuda_runtime.h>
#include <cuda.h>
#include <cstdint>

#define T_TOK 8192
#define DIMK 7168
#define ED 1024
#define NCMP 2048
#define HEAD_DIM_ 512
#define ROPE_DIM_ 64
#define NOPE_DIM_ 448
#define NUM_SLOTS_ 65536
#define EPS_ 1e-6f

// cluster (4,1,1): pairs {0,1},{2,3} do cg2 MMA (M=256 each); cluster M=512, N=256
// B multicast groups {0,2} (half 0), {1,3} (half 1)
#define BM 128               // M rows per CTA
#define BN 256               // N per pair
#define BNH 128              // B rows held per CTA
#define BK 32
#define NK (DIMK / BK)                        // 224
#define NSTAGE 4
#define A_OFF 0
#define BP_OFF (BM * BK * 4)                  // 16384
#define BG_OFF (BP_OFF + BNH * BK * 4)        // 32768
#define STAGE_BYTES (BG_OFF + BNH * BK * 4)   // 49152 per CTA
#define TX_PER_CTA STAGE_BYTES                // per-CTA full bar: own A + mcast B halves
#define SMEM_DYN (NSTAGE * STAGE_BYTES + 1024) // 197632

// idesc cg2: dtype=F32(1), atype=btype=TF32(2), N=256, M=256
#define IDESC ((1u << 4) | (2u << 7) | (2u << 10) | ((BN / 8) << 17) | ((256 / 16) << 24))

#if defined(__CUDA_ARCH_FEAT_SM103_ALL) || defined(__CUDA_ARCH_FEAT_SM100_ALL) || \
    (defined(__CUDA_ARCH_SPECIFIC__) && (__CUDA_ARCH_SPECIFIC__ >= 1000))
#define HAS_TCGEN05 1
#else
#define HAS_TCGEN05 0
#endif

__device__ float g_kv_pre[(size_t)NCMP * ED];
__device__ float g_wkv_r[(size_t)ED * DIMK];
__device__ float g_wgate_r[(size_t)ED * DIMK];

// ---------------------------------------------------------------------------
__device__ __forceinline__ uint32_t smem_u32(const void* p) {
    return (uint32_t)__cvta_generic_to_shared(p);
}
__device__ __forceinline__ uint32_t ctarank() {
    uint32_t r; asm("mov.u32 %0, %%cluster_ctarank;" : "=r"(r)); return r;
}
__device__ __forceinline__ uint64_t make_desc(uint32_t addr) {
    const uint64_t base = (2ull << 61) | (1ull << 46) | (64ull << 32) | (1ull << 16);
    return base | ((uint64_t)(addr >> 4) & 0x3FFF);
}
__device__ __forceinline__ void mbar_init(uint32_t mbar, uint32_t count) {
    asm volatile("mbarrier.init.shared.b64 [%0], %1;" :: "r"(mbar), "r"(count) : "memory");
}
__device__ __forceinline__ void mbar_expect_tx(uint32_t mbar, uint32_t bytes) {
    asm volatile("mbarrier.arrive.expect_tx.shared.b64 _, [%0], %1;"
                 :: "r"(mbar), "r"(bytes) : "memory");
}
__device__ __forceinline__ void mbar_wait(uint32_t mbar, uint32_t parity) {
    asm volatile(
        "{\n\t.reg .pred P1;\n\t"
        "WAIT_%=:\n\t"
        "mbarrier.try_wait.parity.acquire.cta.shared::cta.b64 P1, [%0], %1, 0x989680;\n\t"
        "@P1 bra DONE_%=;\n\t"
        "bra WAIT_%=;\n\t"
        "DONE_%=:\n\t}"
        :: "r"(mbar), "r"(parity) : "memory");
}
__device__ __forceinline__ void mbar_inval(uint32_t mbar) {
    asm volatile("mbarrier.inval.shared.b64 [%0];" :: "r"(mbar) : "memory");
}
// release-arrive on the same-offset mbarrier in another cluster CTA
__device__ __forceinline__ void mbar_arrive_cluster(uint32_t local_mbar, uint32_t target_rank) {
    asm volatile(
        "{\n\t.reg .b32 ra;\n\t"
        "mapa.shared::cluster.u32 ra, %0, %1;\n\t"
        "mbarrier.arrive.release.cluster.shared::cluster.b64 _, [ra];\n\t}"
        :: "r"(local_mbar), "r"(target_rank) : "memory");
}
#define CLUSTER_SYNC() do { \
    asm volatile("barrier.cluster.arrive.aligned;" ::: "memory"); \
    asm volatile("barrier.cluster.wait.aligned;" ::: "memory"); \
} while (0)

// plain per-CTA TMA (A tiles)
__device__ __forceinline__ void tma2d(uint32_t dst, const CUtensorMap* map,
                                      int cx, int cy, uint32_t mbar) {
    asm volatile(
        "cp.async.bulk.tensor.2d.shared::cta.global.tile.mbarrier::complete_tx::bytes "
        "[%0], [%1, {%2, %3}], [%4];"
        :: "r"(dst), "l"(map), "r"(cx), "r"(cy), "r"(mbar) : "memory");
}
// multicast TMA (B tiles): data + complete_tx to same offsets in every masked CTA
__device__ __forceinline__ void tma2d_mc(uint32_t dst, const CUtensorMap* map,
                                         int cx, int cy, uint32_t mbar, uint16_t mask) {
    asm volatile(
        "cp.async.bulk.tensor.2d.shared::cluster.global.tile."
        "mbarrier::complete_tx::bytes.multicast::cluster "
        "[%0], [%1, {%2, %3}], [%4], %5;"
        :: "r"(dst), "l"(map), "r"(cx), "r"(cy), "r"(mbar), "h"(mask) : "memory");
}

#if HAS_TCGEN05
__device__ __forceinline__ void mma_tf32_cg2(uint32_t d_tmem, uint64_t a_desc,
                                             uint64_t b_desc, uint32_t idesc, uint32_t en) {
    asm volatile(
        "{\n\t.reg .pred p;\n\t"
        "setp.ne.u32 p, %5, 0;\n\t"
        "tcgen05.mma.cta_group::2.kind::tf32 [%0], %1, %2, %3, "
        "{%4, %4, %4, %4, %4, %4, %4, %4}, p;\n\t}"
        :: "r"(d_tmem), "l"(a_desc), "l"(b_desc), "r"(idesc), "r"(0u), "r"(en)
        : "memory");
}
__device__ __forceinline__ void tcg_commit_mc(uint32_t mbar, uint16_t mask) {
    asm volatile(
        "tcgen05.commit.cta_group::2.mbarrier::arrive::one.shared::cluster."
        "multicast::cluster.b64 [%0], %1;"
        :: "r"(mbar), "h"(mask) : "memory");
}
#define TCG_ALLOC_CG2(sm_addr, n) \
    asm volatile("tcgen05.alloc.cta_group::2.sync.aligned.shared::cta.b32 [%0], %1;" \
                 :: "r"(sm_addr), "r"(n) : "memory")
#define TCG_DEALLOC_CG2(tmem, n) \
    asm volatile("tcgen05.dealloc.cta_group::2.sync.aligned.b32 %0, %1;" :: "r"(tmem), "r"(n))
#define TCG_RELINQ_CG2() \
    asm volatile("tcgen05.relinquish_alloc_permit.cta_group::2.sync.aligned;")
#define TCG_FENCE_AFTER()  asm volatile("tcgen05.fence::after_thread_sync;" ::: "memory")
#define TCG_WAIT_LD()      asm volatile("tcgen05.wait::ld.sync.aligned;" ::: "memory")

#define TCG_LD_X32(r, addr) \
    asm volatile( \
        "tcgen05.ld.sync.aligned.32x32b.x32.b32 " \
        "{%0, %1, %2, %3, %4, %5, %6, %7, " \
        " %8, %9, %10, %11, %12, %13, %14, %15, " \
        " %16, %17, %18, %19, %20, %21, %22, %23, " \
        " %24, %25, %26, %27, %28, %29, %30, %31}, [%32];" \
        : "=r"((r)[0]),  "=r"((r)[1]),  "=r"((r)[2]),  "=r"((r)[3]), \
          "=r"((r)[4]),  "=r"((r)[5]),  "=r"((r)[6]),  "=r"((r)[7]), \
          "=r"((r)[8]),  "=r"((r)[9]),  "=r"((r)[10]), "=r"((r)[11]), \
          "=r"((r)[12]), "=r"((r)[13]), "=r"((r)[14]), "=r"((r)[15]), \
          "=r"((r)[16]), "=r"((r)[17]), "=r"((r)[18]), "=r"((r)[19]), \
          "=r"((r)[20]), "=r"((r)[21]), "=r"((r)[22]), "=r"((r)[23]), \
          "=r"((r)[24]), "=r"((r)[25]), "=r"((r)[26]), "=r"((r)[27]), \
          "=r"((r)[28]), "=r"((r)[29]), "=r"((r)[30]), "=r"((r)[31]) \
        : "r"(addr))
#endif  // HAS_TCGEN05

// ---------------------------------------------------------------------------
__device__ __forceinline__ float rna_tf32(float f) {
    uint32_t u;
    asm("cvt.rna.tf32.f32 %0, %1;" : "=r"(u) : "f"(f));
    return __uint_as_float(u);
}

__global__ __launch_bounds__(256) void round_weights_kernel(
    const float* __restrict__ wkv, const float* __restrict__ wgate)
{
    size_t i = (size_t)blockIdx.x * blockDim.x + threadIdx.x;
    float4 a = reinterpret_cast<const float4*>(wkv)[i];
    float4 b = reinterpret_cast<const float4*>(wgate)[i];
    a.x = rna_tf32(a.x); a.y = rna_tf32(a.y); a.z = rna_tf32(a.z); a.w = rna_tf32(a.w);
    b.x = rna_tf32(b.x); b.y = rna_tf32(b.y); b.z = rna_tf32(b.z); b.w = rna_tf32(b.w);
    reinterpret_cast<float4*>(g_wkv_r)[i] = a;
    reinterpret_cast<float4*>(g_wgate_r)[i] = b;
}

// ---------------------------------------------------------------------------
// 4-CTA cluster: 2× cg2 dual-GEMM pairs sharing B via TMA multicast
// ---------------------------------------------------------------------------
__global__ __launch_bounds__(256, 1) __cluster_dims__(4, 1, 1) void gemm_tc_kernel(
    const __grid_constant__ CUtensorMap tmx,
    const __grid_constant__ CUtensorMap tmk,
    const __grid_constant__ CUtensorMap tmg,
    const float* __restrict__ x,
    const float* __restrict__ ape)
{
    extern __shared__ float dsm[];
    const int tid  = threadIdx.x;
    const uint32_t rank = ctarank();
    const uint32_t half = rank & 1;          // B half / pair-local role
    const int e0 = (blockIdx.x >> 2) * BN;
    const int t0 = blockIdx.y * 512 + (rank >> 1) * 256 + half * BM;
    const int eb = e0 + half * BNH;

#if HAS_TCGEN05
    __shared__ uint32_t s_tmem;
    __shared__ __align__(8) uint64_t s_mbar[2 * NSTAGE];  // full[0..3], empty[0..3]

    const int warp = tid >> 5;
    const int lane = tid & 31;
    const bool is_mma_leader = (half == 0);          // even rank: issues cg2 MMA
    const bool is_b_loader   = (rank < 2);           // CTAs 0,1 issue B multicast
    const uint16_t bmask = (uint16_t)((1u << rank) | (1u << (rank + 2)));  // {r, r+2}
    const uint32_t leader_rank = rank & ~1u;

    const uint32_t sb_raw = smem_u32(dsm);
    const uint32_t base   = (sb_raw + 1023u) & ~1023u;
    uint32_t mb_full[NSTAGE], mb_empty[NSTAGE];
#pragma unroll
    for (int s = 0; s < NSTAGE; s++) {
        mb_full[s]  = smem_u32(&s_mbar[s]);
        mb_empty[s] = smem_u32(&s_mbar[NSTAGE + s]);
    }

    if (warp == 0) TCG_ALLOC_CG2(smem_u32(&s_tmem), 512);
    if (tid == 0) {
#pragma unroll
        for (int s = 0; s < NSTAGE; s++) {
            // full: leader needs expect(1) + peer arrive(1); peer just expect(1)
            mbar_init(mb_full[s], is_mma_leader ? 2 : 1);
            // empty: one commit from each pair-leader (multicast 0xF)
            mbar_init(mb_empty[s], 2);
            // arm all prefetch stages before any TMA can land
            mbar_expect_tx(mb_full[s], TX_PER_CTA);
        }
    }
    __syncthreads();
    CLUSTER_SYNC();   // inits + expects visible cluster-wide
    const uint32_t tmem = s_tmem;   // proj @ cols [0,256), gate @ cols [256,512)

    if (tid == 0) {
        // prefetch tiles 0..3
#pragma unroll
        for (int s = 0; s < NSTAGE; s++) {
            const uint32_t sa = base + s * STAGE_BYTES;
            tma2d(sa + A_OFF, &tmx, s * BK, t0, mb_full[s]);
            if (is_b_loader) {
                tma2d_mc(sa + BP_OFF, &tmk, s * BK, eb, mb_full[s], bmask);
                tma2d_mc(sa + BG_OFF, &tmg, s * BK, eb, mb_full[s], bmask);
            }
        }
        int phf[NSTAGE] = {0, 0, 0, 0};
        int phe[NSTAGE] = {0, 0, 0, 0};
#pragma unroll 1
        for (int kt = 0; kt < NK; kt++) {
            const int s = kt & (NSTAGE - 1);
            // consume stage s
            mbar_wait(mb_full[s], phf[s]); phf[s] ^= 1;
            // re-arm BEFORE anything that can gate a refill targeting this CTA
            if (kt + NSTAGE < NK) mbar_expect_tx(mb_full[s], TX_PER_CTA);
            if (is_mma_leader) {
                const uint32_t sa = base + s * STAGE_BYTES;
                const uint64_t ad  = make_desc(sa + A_OFF);
                const uint64_t bpd = make_desc(sa + BP_OFF);
                const uint64_t bgd = make_desc(sa + BG_OFF);
                const uint32_t en0 = (kt > 0);
#pragma unroll
                for (int ks = 0; ks < 4; ks++) {
                    const uint32_t en = en0 | (uint32_t)(ks > 0);
                    mma_tf32_cg2(tmem,      ad + 2 * ks, bpd + 2 * ks, IDESC, en);
                    mma_tf32_cg2(tmem + BN, ad + 2 * ks, bgd + 2 * ks, IDESC, en);
                }
                tcg_commit_mc(mb_empty[s], 0xF);   // both pairs' commits -> all empties
            } else {
                // peer: signal pair leader that this CTA's stage-s tiles are ready
                mbar_arrive_cluster(mb_full[s], leader_rank);
            }
            // delayed refill: stage committed LAST iteration gets tile kt+3
            if (kt >= 1 && kt + NSTAGE - 1 < NK) {
                const int rs = (kt - 1) & (NSTAGE - 1);
                mbar_wait(mb_empty[rs], phe[rs]); phe[rs] ^= 1;
                const uint32_t sa = base + rs * STAGE_BYTES;
                const int k0 = (kt + NSTAGE - 1) * BK;
                tma2d(sa + A_OFF, &tmx, k0, t0, mb_full[rs]);
                if (is_b_loader) {
                    tma2d_mc(sa + BP_OFF, &tmk, k0, eb, mb_full[rs], bmask);
                    tma2d_mc(sa + BG_OFF, &tmg, k0, eb, mb_full[rs], bmask);
                }
            }
        }
        // last commits (both pairs) imply all MMAs complete
        const int ls = (NK - 1) & (NSTAGE - 1);
        mbar_wait(mb_empty[ls], phe[ls]);
    }
    __syncthreads();
    TCG_FENCE_AFTER();

    // ---- epilogue: warps 0-3 read local TMEM (lane -> local M row)
    float* vt = (float*)((char*)dsm + (base - sb_raw));  // [32][257]
    if (warp < 4) {
#pragma unroll 1
        for (int cb = 0; cb < 8; cb++) {
            uint32_t pr[32], gr[32];
            TCG_LD_X32(pr, tmem + cb * 32);
            TCG_LD_X32(gr, tmem + BN + cb * 32);
            TCG_WAIT_LD();
            float v[32];
#pragma unroll
            for (int i = 0; i < 32; i++) {
                float p = __uint_as_float(pr[i]);
                float g = __uint_as_float(gr[i]);
                v[i] = p / (1.f + __expf(-g));
            }
#pragma unroll
            for (int i = 0; i < 32; i++) {
                v[i] += __shfl_xor_sync(0xffffffffu, v[i], 1);
                v[i] += __shfl_xor_sync(0xffffffffu, v[i], 2);
            }
            if ((lane & 3) == 0) {
                int row = warp * 8 + (lane >> 2);
#pragma unroll
                for (int i = 0; i < 32; i++) vt[row * 257 + cb * 32 + i] = v[i];
            }
        }
    }
    __syncthreads();

    {
        const int e = e0 + tid;
        const float asum = ape[e] + ape[ED + e] + ape[2 * ED + e] + ape[3 * ED + e];
        const int n0 = t0 >> 2;
#pragma unroll 4
        for (int row = 0; row < 32; row++) {
            float s = vt[row * 257 + tid];
            g_kv_pre[(size_t)(n0 + row) * ED + e] = 0.25f * (s + asum);
        }
    }
    __syncthreads();
    if (tid == 0) {
#pragma unroll
        for (int s = 0; s < NSTAGE; s++) { mbar_inval(mb_full[s]); mbar_inval(mb_empty[s]); }
    }
    __syncthreads();
    if (warp == 0) { TCG_RELINQ_CG2(); TCG_DEALLOC_CG2(tmem, 512); }
    CLUSTER_SYNC();

#else  // ---- generic-PTX fallback (correct, never executed on GB300) ----
    const int n0 = t0 >> 2;
    for (int idx = tid; idx < 32 * BN; idx += 256) {
        int row = idx / BN, col = idx % BN;
        int e = e0 + col;
        float acc = 0.f;
        for (int r = 0; r < 4; r++) {
            const float* xr = x + (size_t)(t0 + row * 4 + r) * DIMK;
            const float* wk = g_wkv_r + (size_t)e * DIMK;
            const float* wg = g_wgate_r + (size_t)e * DIMK;
            float p = 0.f, g = 0.f;
            for (int k = 0; k < DIMK; k++) { p += xr[k] * wk[k]; g += xr[k] * wg[k]; }
            acc += p / (1.f + __expf(-g));
        }
        float asum = ape[e] + ape[ED + e] + ape[2 * ED + e] + ape[3 * ED + e];
        g_kv_pre[(size_t)(n0 + row) * ED + e] = 0.25f * (acc + asum);
    }
    (void)dsm;
#endif
}

// ---------------------------------------------------------------------------
// RMS-norm (per 512) + partial RoPE + scatter
// ---------------------------------------------------------------------------
__global__ __launch_bounds__(256) void norm_rope_scatter_kernel(
    const float* __restrict__ norm_weight, const float* __restrict__ rope_cos,
    const float* __restrict__ rope_sin, const int* __restrict__ slot_mapping,
    float* __restrict__ out)
{
    __shared__ float vals[ED];
    __shared__ float wsum[8];
    const int n = blockIdx.x;
    const int tid = threadIdx.x;

    float4 v = reinterpret_cast<const float4*>(g_kv_pre)[(size_t)n * 256 + tid];
    float ssq = v.x * v.x + v.y * v.y + v.z * v.z + v.w * v.w;
#pragma unroll
    for (int off = 16; off > 0; off >>= 1)
        ssq += __shfl_xor_sync(0xffffffffu, ssq, off);
    if ((tid & 31) == 0) wsum[tid >> 5] = ssq;
    __syncthreads();

    const int c = tid >> 7;
    float tot = wsum[c * 4] + wsum[c * 4 + 1] + wsum[c * 4 + 2] + wsum[c * 4 + 3];
    float scale = rsqrtf(tot * (1.0f / HEAD_DIM_) + EPS_);
    float4 nw = reinterpret_cast<const float4*>(norm_weight)[tid & 127];
    v.x *= scale * nw.x; v.y *= scale * nw.y; v.z *= scale * nw.z; v.w *= scale * nw.w;
    reinterpret_cast<float4*>(vals)[tid] = v;
    __syncthreads();

    const int din = tid & 127;
    if (din >= 112) {
        int rd = (din - 112) * 4;
        const float* cb = rope_cos + (size_t)n * ROPE_DIM_;
        const float* sb = rope_sin + (size_t)n * ROPE_DIM_;
        float vv[4] = {v.x, v.y, v.z, v.w};
#pragma unroll
        for (int j = 0; j < 4; j++) {
            int rdj = rd + j;
            float partner = (rdj < 32)
                ? -vals[c * HEAD_DIM_ + NOPE_DIM_ + rdj + 32]
                :  vals[c * HEAD_DIM_ + NOPE_DIM_ + rdj - 32];
            vv[j] = vv[j] * cb[rdj] + partner * sb[rdj];
        }
        v.x = vv[0]; v.y = vv[1]; v.z = vv[2]; v.w = vv[3];
    }

    const int slot = slot_mapping[n];
    reinterpret_cast<float4*>(out)[(size_t)slot * 256 + tid] = v;
}

// ---------------------------------------------------------------------------
// host side
// ---------------------------------------------------------------------------
typedef CUresult (*PFN_encodeTiled)(
    CUtensorMap*, CUtensorMapDataType, cuuint32_t, void*,
    const cuuint64_t*, const cuuint64_t*, const cuuint32_t*, const cuuint32_t*,
    CUtensorMapInterleave, CUtensorMapSwizzle, CUtensorMapL2promotion,
    CUtensorMapFloatOOBfill);

static void encode_map(PFN_encodeTiled fn, CUtensorMap* tm, void* p,
                       uint64_t d0, uint64_t d1, uint32_t b0, uint32_t b1) {
    cuuint64_t dims[2]    = {d0, d1};
    cuuint64_t strides[1] = {d0 * 4};
    cuuint32_t box[2]     = {b0, b1};
    cuuint32_t estr[2]    = {1, 1};
    fn(tm, CU_TENSOR_MAP_DATA_TYPE_FLOAT32, 2, p, dims, strides, box, estr,
       CU_TENSOR_MAP_INTERLEAVE_NONE, CU_TENSOR_MAP_SWIZZLE_128B,
       CU_TENSOR_MAP_L2_PROMOTION_L2_128B, CU_TENSOR_MAP_FLOAT_OOB_FILL_NONE);
}

extern "C" void kernel_launch(void* const* d_in, const int* in_sizes, int n_in,
                              void* d_out, int out_size) {
    const float* x     = (const float*)d_in[0];
    const float* wkv   = (const float*)d_in[1];
    const float* wgate = (const float*)d_in[2];
    const float* ape   = (const float*)d_in[3];
    const float* nw    = (const float*)d_in[4];
    const float* rcos  = (const float*)d_in[5];
    const float* rsin  = (const float*)d_in[6];
    const float* cache = (const float*)d_in[7];
    const int*   slots = (const int*)d_in[8];
    float* out = (float*)d_out;

    void* fptr = nullptr;
    cudaDriverEntryPointQueryResult qr;
    cudaGetDriverEntryPointByVersion("cuTensorMapEncodeTiled", &fptr, 12000,
                                     cudaEnableDefault, &qr);
    PFN_encodeTiled enc = (PFN_encodeTiled)fptr;

    void *wkv_r_ptr = nullptr, *wgate_r_ptr = nullptr;
    cudaGetSymbolAddress(&wkv_r_ptr, g_wkv_r);
    cudaGetSymbolAddress(&wgate_r_ptr, g_wgate_r);

    CUtensorMap tmx, tmk, tmg;
    encode_map(enc, &tmx, (void*)x,    DIMK, T_TOK, BK, BM);
    encode_map(enc, &tmk, wkv_r_ptr,   DIMK, ED,    BK, BNH);
    encode_map(enc, &tmg, wgate_r_ptr, DIMK, ED,    BK, BNH);

    cudaFuncSetAttribute(gemm_tc_kernel,
                         cudaFuncAttributeMaxDynamicSharedMemorySize, SMEM_DYN);

    // fork the big cache copy onto a side stream so it overlaps the GEMM
    static cudaStream_t s_copy = nullptr;
    static cudaEvent_t ev_fork = nullptr, ev_join = nullptr;
    if (s_copy == nullptr) {
        cudaStreamCreateWithFlags(&s_copy, cudaStreamNonBlocking);
        cudaEventCreateWithFlags(&ev_fork, cudaEventDisableTiming);
        cudaEventCreateWithFlags(&ev_join, cudaEventDisableTiming);
    }
    cudaEventRecord(ev_fork, 0);
    cudaStreamWaitEvent(s_copy, ev_fork, 0);
    cudaMemcpyAsync(out, cache, (size_t)NUM_SLOTS_ * ED * sizeof(float),
                    cudaMemcpyDeviceToDevice, s_copy);
    cudaEventRecord(ev_join, s_copy);

    round_weights_kernel<<<(ED * DIMK / 4) / 256, 256>>>(wkv, wgate);

    dim3 grid(4 * (ED / BN), T_TOK / 512);  // (16, 16), cluster (4,1,1) along x
    gemm_tc_kernel<<<grid, 256, SMEM_DYN>>>(tmx, tmk, tmg, x, ape);

    cudaStreamWaitEvent(0, ev_join, 0);  // copy must land before scatter
    norm_rope_scatter_kernel<<<NCMP, 256>>>(nw, rcos, rsin, slots, out);
}

// round 7
// speedup vs baseline: 1.3766x; 1.3766x over previous
#include <cuda_runtime.h>
#include <cuda.h>
#include <cstdint>

#define T_TOK 8192
#define DIMK 7168
#define ED 1024
#define NCMP 2048
#define HEAD_DIM_ 512
#define ROPE_DIM_ 64
#define NOPE_DIM_ 448
#define NUM_SLOTS_ 65536
#define EPS_ 1e-6f

// GEMM tiling: cta_group::2, M=256 per cluster pair (128 rows per CTA), N=256
#define BM 128               // M rows per CTA
#define BN 256               // N per pair (B split: 128 rows per CTA)
#define BNH 128              // B rows held per CTA
#define BK 32
#define NK (DIMK / BK)                        // 224
#define NSTAGE 4
#define A_OFF 0
#define BP_OFF (BM * BK * 4)                  // 16384
#define BG_OFF (BP_OFF + BNH * BK * 4)        // 32768
#define STAGE_BYTES (BG_OFF + BNH * BK * 4)   // 49152 per CTA
#define TX_TOTAL (2 * STAGE_BYTES)            // 98304 (both CTAs -> leader bar)
#define SMEM_DYN (NSTAGE * STAGE_BYTES + 1024) // 197632

// idesc cg2: dtype=F32(1), atype=btype=TF32(2), N=256, M=256
#define IDESC ((1u << 4) | (2u << 7) | (2u << 10) | ((BN / 8) << 17) | ((256 / 16) << 24))

#if defined(__CUDA_ARCH_FEAT_SM103_ALL) || defined(__CUDA_ARCH_FEAT_SM100_ALL) || \
    (defined(__CUDA_ARCH_SPECIFIC__) && (__CUDA_ARCH_SPECIFIC__ >= 1000))
#define HAS_TCGEN05 1
#else
#define HAS_TCGEN05 0
#endif

__device__ float g_kv_pre[(size_t)NCMP * ED];
__device__ float g_wkv_r[(size_t)ED * DIMK];
__device__ float g_wgate_r[(size_t)ED * DIMK];

// ---------------------------------------------------------------------------
__device__ __forceinline__ uint32_t smem_u32(const void* p) {
    return (uint32_t)__cvta_generic_to_shared(p);
}
__device__ __forceinline__ uint32_t ctarank() {
    uint32_t r; asm("mov.u32 %0, %%cluster_ctarank;" : "=r"(r)); return r;
}
__device__ __forceinline__ uint64_t make_desc(uint32_t addr) {
    const uint64_t base = (2ull << 61) | (1ull << 46) | (64ull << 32) | (1ull << 16);
    return base | ((uint64_t)(addr >> 4) & 0x3FFF);
}
__device__ __forceinline__ void mbar_init(uint32_t mbar, uint32_t count) {
    asm volatile("mbarrier.init.shared.b64 [%0], %1;" :: "r"(mbar), "r"(count) : "memory");
}
__device__ __forceinline__ void mbar_expect_tx(uint32_t mbar, uint32_t bytes) {
    asm volatile("mbarrier.arrive.expect_tx.shared.b64 _, [%0], %1;"
                 :: "r"(mbar), "r"(bytes) : "memory");
}
__device__ __forceinline__ void mbar_wait(uint32_t mbar, uint32_t parity) {
    asm volatile(
        "{\n\t.reg .pred P1;\n\t"
        "WAIT_%=:\n\t"
        "mbarrier.try_wait.parity.acquire.cta.shared::cta.b64 P1, [%0], %1, 0x989680;\n\t"
        "@P1 bra DONE_%=;\n\t"
        "bra WAIT_%=;\n\t"
        "DONE_%=:\n\t}"
        :: "r"(mbar), "r"(parity) : "memory");
}
__device__ __forceinline__ void mbar_inval(uint32_t mbar) {
    asm volatile("mbarrier.inval.shared.b64 [%0];" :: "r"(mbar) : "memory");
}
#define CLUSTER_SYNC() do { \
    asm volatile("barrier.cluster.arrive.aligned;" ::: "memory"); \
    asm volatile("barrier.cluster.wait.aligned;" ::: "memory"); \
} while (0)

#if HAS_TCGEN05
__device__ __forceinline__ void tma2d_cg2(uint32_t dst, const CUtensorMap* map,
                                          int cx, int cy, uint32_t mbar) {
    asm volatile(
        "{\n\t.reg .b32 lb;\n\t"
        "and.b32 lb, %4, 0xFEFFFFFF;\n\t"
        "cp.async.bulk.tensor.2d.cta_group::2.shared::cluster.global.tile."
        "mbarrier::complete_tx::bytes [%0], [%1, {%2, %3}], [lb];\n\t}"
        :: "r"(dst), "l"(map), "r"(cx), "r"(cy), "r"(mbar) : "memory");
}
__device__ __forceinline__ void mma_tf32_cg2(uint32_t d_tmem, uint64_t a_desc,
                                             uint64_t b_desc, uint32_t idesc, uint32_t en) {
    asm volatile(
        "{\n\t.reg .pred p;\n\t"
        "setp.ne.u32 p, %5, 0;\n\t"
        "tcgen05.mma.cta_group::2.kind::tf32 [%0], %1, %2, %3, "
        "{%4, %4, %4, %4, %4, %4, %4, %4}, p;\n\t}"
        :: "r"(d_tmem), "l"(a_desc), "l"(b_desc), "r"(idesc), "r"(0u), "r"(en)
        : "memory");
}
__device__ __forceinline__ void tcg_commit_mc(uint32_t mbar, uint16_t mask) {
    asm volatile(
        "tcgen05.commit.cta_group::2.mbarrier::arrive::one.shared::cluster."
        "multicast::cluster.b64 [%0], %1;"
        :: "r"(mbar), "h"(mask) : "memory");
}
#define TCG_ALLOC_CG2(sm_addr, n) \
    asm volatile("tcgen05.alloc.cta_group::2.sync.aligned.shared::cta.b32 [%0], %1;" \
                 :: "r"(sm_addr), "r"(n) : "memory")
#define TCG_DEALLOC_CG2(tmem, n) \
    asm volatile("tcgen05.dealloc.cta_group::2.sync.aligned.b32 %0, %1;" :: "r"(tmem), "r"(n))
#define TCG_RELINQ_CG2() \
    asm volatile("tcgen05.relinquish_alloc_permit.cta_group::2.sync.aligned;")
#define TCG_FENCE_AFTER()  asm volatile("tcgen05.fence::after_thread_sync;" ::: "memory")
#define TCG_WAIT_LD()      asm volatile("tcgen05.wait::ld.sync.aligned;" ::: "memory")

#define TCG_LD_X32(r, addr) \
    asm volatile( \
        "tcgen05.ld.sync.aligned.32x32b.x32.b32 " \
        "{%0, %1, %2, %3, %4, %5, %6, %7, " \
        " %8, %9, %10, %11, %12, %13, %14, %15, " \
        " %16, %17, %18, %19, %20, %21, %22, %23, " \
        " %24, %25, %26, %27, %28, %29, %30, %31}, [%32];" \
        : "=r"((r)[0]),  "=r"((r)[1]),  "=r"((r)[2]),  "=r"((r)[3]), \
          "=r"((r)[4]),  "=r"((r)[5]),  "=r"((r)[6]),  "=r"((r)[7]), \
          "=r"((r)[8]),  "=r"((r)[9]),  "=r"((r)[10]), "=r"((r)[11]), \
          "=r"((r)[12]), "=r"((r)[13]), "=r"((r)[14]), "=r"((r)[15]), \
          "=r"((r)[16]), "=r"((r)[17]), "=r"((r)[18]), "=r"((r)[19]), \
          "=r"((r)[20]), "=r"((r)[21]), "=r"((r)[22]), "=r"((r)[23]), \
          "=r"((r)[24]), "=r"((r)[25]), "=r"((r)[26]), "=r"((r)[27]), \
          "=r"((r)[28]), "=r"((r)[29]), "=r"((r)[30]), "=r"((r)[31]) \
        : "r"(addr))
#endif  // HAS_TCGEN05

// ---------------------------------------------------------------------------
__device__ __forceinline__ float rna_tf32(float f) {
    uint32_t u;
    asm("cvt.rna.tf32.f32 %0, %1;" : "=r"(u) : "f"(f));
    return __uint_as_float(u);
}

__global__ __launch_bounds__(256) void round_weights_kernel(
    const float* __restrict__ wkv, const float* __restrict__ wgate)
{
    size_t i = (size_t)blockIdx.x * blockDim.x + threadIdx.x;
    float4 a = reinterpret_cast<const float4*>(wkv)[i];
    float4 b = reinterpret_cast<const float4*>(wgate)[i];
    a.x = rna_tf32(a.x); a.y = rna_tf32(a.y); a.z = rna_tf32(a.z); a.w = rna_tf32(a.w);
    b.x = rna_tf32(b.x); b.y = rna_tf32(b.y); b.z = rna_tf32(b.z); b.w = rna_tf32(b.w);
    reinterpret_cast<float4*>(g_wkv_r)[i] = a;
    reinterpret_cast<float4*>(g_wgate_r)[i] = b;
}

// ---------------------------------------------------------------------------
// 2CTA tcgen05 dual-GEMM, 4-stage pipeline with delayed refill (R5 structure)
// ---------------------------------------------------------------------------
__global__ __launch_bounds__(256, 1) __cluster_dims__(2, 1, 1) void gemm_tc_kernel(
    const __grid_constant__ CUtensorMap tmx,
    const __grid_constant__ CUtensorMap tmk,
    const __grid_constant__ CUtensorMap tmg,
    const float* __restrict__ x,
    const float* __restrict__ ape)
{
    extern __shared__ float dsm[];
    const int tid  = threadIdx.x;
    const uint32_t rank = ctarank();
    const int e0 = (blockIdx.x >> 1) * BN;
    const int t0 = blockIdx.y * 256 + rank * BM;
    const int eb = e0 + rank * BNH;

#if HAS_TCGEN05
    __shared__ uint32_t s_tmem;
    __shared__ __align__(8) uint64_t s_mbar[2 * NSTAGE];  // full[0..3], empty[0..3]

    const int warp = tid >> 5;
    const int lane = tid & 31;
    const bool leader = (rank == 0);

    const uint32_t sb_raw = smem_u32(dsm);
    const uint32_t base   = (sb_raw + 1023u) & ~1023u;
    uint32_t mb_full[NSTAGE], mb_empty[NSTAGE];
#pragma unroll
    for (int s = 0; s < NSTAGE; s++) {
        mb_full[s]  = smem_u32(&s_mbar[s]);
        mb_empty[s] = smem_u32(&s_mbar[NSTAGE + s]);
    }

    if (warp == 0) TCG_ALLOC_CG2(smem_u32(&s_tmem), 512);
    if (tid == 0) {
#pragma unroll
        for (int s = 0; s < NSTAGE; s++) {
            mbar_init(mb_full[s], 1);
            mbar_init(mb_empty[s], 1);
        }
        if (leader) {  // arm all prefetch stages before any peer TMA can land
#pragma unroll
            for (int s = 0; s < NSTAGE; s++) mbar_expect_tx(mb_full[s], TX_TOTAL);
        }
    }
    __syncthreads();
    CLUSTER_SYNC();   // inits + expects visible cluster-wide
    const uint32_t tmem = s_tmem;   // proj @ cols [0,256), gate @ cols [256,512)

    if (tid == 0) {
        // prefetch tiles 0..3 (both ranks; completion -> leader's full bars)
#pragma unroll
        for (int s = 0; s < NSTAGE; s++) {
            const uint32_t sa = base + s * STAGE_BYTES;
            tma2d_cg2(sa + A_OFF,  &tmx, s * BK, t0, mb_full[s]);
            tma2d_cg2(sa + BP_OFF, &tmk, s * BK, eb, mb_full[s]);
            tma2d_cg2(sa + BG_OFF, &tmg, s * BK, eb, mb_full[s]);
        }
        int phf[NSTAGE] = {0, 0, 0, 0};
        int phe[NSTAGE] = {0, 0, 0, 0};
#pragma unroll 1
        for (int kt = 0; kt < NK; kt++) {
            const int s = kt & (NSTAGE - 1);
            if (leader) {
                mbar_wait(mb_full[s], phf[s]); phf[s] ^= 1;
                const uint32_t sa = base + s * STAGE_BYTES;
                const uint64_t ad  = make_desc(sa + A_OFF);
                const uint64_t bpd = make_desc(sa + BP_OFF);
                const uint64_t bgd = make_desc(sa + BG_OFF);
                const uint32_t en0 = (kt > 0);
#pragma unroll
                for (int ks = 0; ks < 4; ks++) {
                    const uint32_t en = en0 | (uint32_t)(ks > 0);
                    mma_tf32_cg2(tmem,      ad + 2 * ks, bpd + 2 * ks, IDESC, en);
                    mma_tf32_cg2(tmem + BN, ad + 2 * ks, bgd + 2 * ks, IDESC, en);
                }
                // re-arm this stage's full bar (tile kt+4 arrives here at kt+1)
                if (kt + NSTAGE < NK) mbar_expect_tx(mb_full[s], TX_TOTAL);
                tcg_commit_mc(mb_empty[s], 0x3);
            }
            // delayed refill: stage committed LAST iteration gets tile kt+3
            if (kt >= 1 && kt + NSTAGE - 1 < NK) {
                const int rs = (kt - 1) & (NSTAGE - 1);
                mbar_wait(mb_empty[rs], phe[rs]); phe[rs] ^= 1;
                const uint32_t sa = base + rs * STAGE_BYTES;
                const int k0 = (kt + NSTAGE - 1) * BK;
                tma2d_cg2(sa + A_OFF,  &tmx, k0, t0, mb_full[rs]);
                tma2d_cg2(sa + BP_OFF, &tmk, k0, eb, mb_full[rs]);
                tma2d_cg2(sa + BG_OFF, &tmg, k0, eb, mb_full[rs]);
            }
        }
        // in-order tcgen05 queue: last commit implies all MMAs complete
        const int ls = (NK - 1) & (NSTAGE - 1);
        mbar_wait(mb_empty[ls], phe[ls]);
    }
    __syncthreads();
    TCG_FENCE_AFTER();

    // ---- epilogue: warps 0-3 read local TMEM (lane -> local M row)
    float* vt = (float*)((char*)dsm + (base - sb_raw));  // [32][257]
    if (warp < 4) {
#pragma unroll 1
        for (int cb = 0; cb < 8; cb++) {
            uint32_t pr[32], gr[32];
            TCG_LD_X32(pr, tmem + cb * 32);
            TCG_LD_X32(gr, tmem + BN + cb * 32);
            TCG_WAIT_LD();
            float v[32];
#pragma unroll
            for (int i = 0; i < 32; i++) {
                float p = __uint_as_float(pr[i]);
                float g = __uint_as_float(gr[i]);
                v[i] = p / (1.f + __expf(-g));
            }
#pragma unroll
            for (int i = 0; i < 32; i++) {
                v[i] += __shfl_xor_sync(0xffffffffu, v[i], 1);
                v[i] += __shfl_xor_sync(0xffffffffu, v[i], 2);
            }
            if ((lane & 3) == 0) {
                int row = warp * 8 + (lane >> 2);
#pragma unroll
                for (int i = 0; i < 32; i++) vt[row * 257 + cb * 32 + i] = v[i];
            }
        }
    }
    __syncthreads();

    {
        const int e = e0 + tid;
        const float asum = ape[e] + ape[ED + e] + ape[2 * ED + e] + ape[3 * ED + e];
        const int n0 = t0 >> 2;
#pragma unroll 4
        for (int row = 0; row < 32; row++) {
            float s = vt[row * 257 + tid];
            g_kv_pre[(size_t)(n0 + row) * ED + e] = 0.25f * (s + asum);
        }
    }
    __syncthreads();
    if (tid == 0) {
#pragma unroll
        for (int s = 0; s < NSTAGE; s++) { mbar_inval(mb_full[s]); mbar_inval(mb_empty[s]); }
    }
    __syncthreads();
    if (warp == 0) { TCG_RELINQ_CG2(); TCG_DEALLOC_CG2(tmem, 512); }
    CLUSTER_SYNC();

#else  // ---- generic-PTX fallback (correct, never executed on GB300) ----
    const int n0 = t0 >> 2;
    for (int idx = tid; idx < 32 * BN; idx += 256) {
        int row = idx / BN, col = idx % BN;
        int e = e0 + col;
        float acc = 0.f;
        for (int r = 0; r < 4; r++) {
            const float* xr = x + (size_t)(t0 + row * 4 + r) * DIMK;
            const float* wk = g_wkv_r + (size_t)e * DIMK;
            const float* wg = g_wgate_r + (size_t)e * DIMK;
            float p = 0.f, g = 0.f;
            for (int k = 0; k < DIMK; k++) { p += xr[k] * wk[k]; g += xr[k] * wg[k]; }
            acc += p / (1.f + __expf(-g));
        }
        float asum = ape[e] + ape[ED + e] + ape[2 * ED + e] + ape[3 * ED + e];
        g_kv_pre[(size_t)(n0 + row) * ED + e] = 0.25f * (acc + asum);
    }
    (void)dsm;
#endif
}

// ---------------------------------------------------------------------------
// RMS-norm (per 512) + partial RoPE + scatter
// ---------------------------------------------------------------------------
__global__ __launch_bounds__(256) void norm_rope_scatter_kernel(
    const float* __restrict__ norm_weight, const float* __restrict__ rope_cos,
    const float* __restrict__ rope_sin, const int* __restrict__ slot_mapping,
    float* __restrict__ out)
{
    __shared__ float vals[ED];
    __shared__ float wsum[8];
    const int n = blockIdx.x;
    const int tid = threadIdx.x;

    float4 v = reinterpret_cast<const float4*>(g_kv_pre)[(size_t)n * 256 + tid];
    float ssq = v.x * v.x + v.y * v.y + v.z * v.z + v.w * v.w;
#pragma unroll
    for (int off = 16; off > 0; off >>= 1)
        ssq += __shfl_xor_sync(0xffffffffu, ssq, off);
    if ((tid & 31) == 0) wsum[tid >> 5] = ssq;
    __syncthreads();

    const int c = tid >> 7;
    float tot = wsum[c * 4] + wsum[c * 4 + 1] + wsum[c * 4 + 2] + wsum[c * 4 + 3];
    float scale = rsqrtf(tot * (1.0f / HEAD_DIM_) + EPS_);
    float4 nw = reinterpret_cast<const float4*>(norm_weight)[tid & 127];
    v.x *= scale * nw.x; v.y *= scale * nw.y; v.z *= scale * nw.z; v.w *= scale * nw.w;
    reinterpret_cast<float4*>(vals)[tid] = v;
    __syncthreads();

    const int din = tid & 127;
    if (din >= 112) {
        int rd = (din - 112) * 4;
        const float* cb = rope_cos + (size_t)n * ROPE_DIM_;
        const float* sb = rope_sin + (size_t)n * ROPE_DIM_;
        float vv[4] = {v.x, v.y, v.z, v.w};
#pragma unroll
        for (int j = 0; j < 4; j++) {
            int rdj = rd + j;
            float partner = (rdj < 32)
                ? -vals[c * HEAD_DIM_ + NOPE_DIM_ + rdj + 32]
                :  vals[c * HEAD_DIM_ + NOPE_DIM_ + rdj - 32];
            vv[j] = vv[j] * cb[rdj] + partner * sb[rdj];
        }
        v.x = vv[0]; v.y = vv[1]; v.z = vv[2]; v.w = vv[3];
    }

    const int slot = slot_mapping[n];
    reinterpret_cast<float4*>(out)[(size_t)slot * 256 + tid] = v;
}

// ---------------------------------------------------------------------------
// host side
// ---------------------------------------------------------------------------
typedef CUresult (*PFN_encodeTiled)(
    CUtensorMap*, CUtensorMapDataType, cuuint32_t, void*,
    const cuuint64_t*, const cuuint64_t*, const cuuint32_t*, const cuuint32_t*,
    CUtensorMapInterleave, CUtensorMapSwizzle, CUtensorMapL2promotion,
    CUtensorMapFloatOOBfill);

static void encode_map(PFN_encodeTiled fn, CUtensorMap* tm, void* p,
                       uint64_t d0, uint64_t d1, uint32_t b0, uint32_t b1) {
    cuuint64_t dims[2]    = {d0, d1};
    cuuint64_t strides[1] = {d0 * 4};
    cuuint32_t box[2]     = {b0, b1};
    cuuint32_t estr[2]    = {1, 1};
    fn(tm, CU_TENSOR_MAP_DATA_TYPE_FLOAT32, 2, p, dims, strides, box, estr,
       CU_TENSOR_MAP_INTERLEAVE_NONE, CU_TENSOR_MAP_SWIZZLE_128B,
       CU_TENSOR_MAP_L2_PROMOTION_L2_128B, CU_TENSOR_MAP_FLOAT_OOB_FILL_NONE);
}

extern "C" void kernel_launch(void* const* d_in, const int* in_sizes, int n_in,
                              void* d_out, int out_size) {
    const float* x     = (const float*)d_in[0];
    const float* wkv   = (const float*)d_in[1];
    const float* wgate = (const float*)d_in[2];
    const float* ape   = (const float*)d_in[3];
    const float* nw    = (const float*)d_in[4];
    const float* rcos  = (const float*)d_in[5];
    const float* rsin  = (const float*)d_in[6];
    const float* cache = (const float*)d_in[7];
    const int*   slots = (const int*)d_in[8];
    float* out = (float*)d_out;

    void* fptr = nullptr;
    cudaDriverEntryPointQueryResult qr;
    cudaGetDriverEntryPointByVersion("cuTensorMapEncodeTiled", &fptr, 12000,
                                     cudaEnableDefault, &qr);
    PFN_encodeTiled enc = (PFN_encodeTiled)fptr;

    void *wkv_r_ptr = nullptr, *wgate_r_ptr = nullptr;
    cudaGetSymbolAddress(&wkv_r_ptr, g_wkv_r);
    cudaGetSymbolAddress(&wgate_r_ptr, g_wgate_r);

    CUtensorMap tmx, tmk, tmg;
    encode_map(enc, &tmx, (void*)x,    DIMK, T_TOK, BK, BM);
    encode_map(enc, &tmk, wkv_r_ptr,   DIMK, ED,    BK, BNH);
    encode_map(enc, &tmg, wgate_r_ptr, DIMK, ED,    BK, BNH);

    cudaFuncSetAttribute(gemm_tc_kernel,
                         cudaFuncAttributeMaxDynamicSharedMemorySize, SMEM_DYN);

    // fork the big cache copy onto a side stream so it overlaps the GEMM
    static cudaStream_t s_copy = nullptr;
    static cudaEvent_t ev_fork = nullptr, ev_join = nullptr;
    if (s_copy == nullptr) {
        cudaStreamCreateWithFlags(&s_copy, cudaStreamNonBlocking);
        cudaEventCreateWithFlags(&ev_fork, cudaEventDisableTiming);
        cudaEventCreateWithFlags(&ev_join, cudaEventDisableTiming);
    }
    cudaEventRecord(ev_fork, 0);
    cudaStreamWaitEvent(s_copy, ev_fork, 0);
    cudaMemcpyAsync(out, cache, (size_t)NUM_SLOTS_ * ED * sizeof(float),
                    cudaMemcpyDeviceToDevice, s_copy);
    cudaEventRecord(ev_join, s_copy);

    round_weights_kernel<<<(ED * DIMK / 4) / 256, 256>>>(wkv, wgate);

    dim3 grid(2 * (ED / BN), T_TOK / 256);  // (8, 32), cluster (2,1,1) along x
    gemm_tc_kernel<<<grid, 256, SMEM_DYN>>>(tmx, tmk, tmg, x, ape);

    cudaStreamWaitEvent(0, ev_join, 0);  // copy must land before scatter
    norm_rope_scatter_kernel<<<NCMP, 256>>>(nw, rcos, rsin, slots, out);
}

// round 8
// speedup vs baseline: 1.6491x; 1.1979x over previous
#include <cuda_runtime.h>
#include <cuda.h>
#include <cuda_fp16.h>
#include <cstdint>

#define T_TOK 8192
#define DIMK 7168
#define ED 1024
#define NCMP 2048
#define HEAD_DIM_ 512
#define ROPE_DIM_ 64
#define NOPE_DIM_ 448
#define NUM_SLOTS_ 65536
#define EPS_ 1e-6f

// GEMM tiling: cta_group::2, M=256/pair, N=256, fp16 operands
#define BM 128               // M rows per CTA
#define BN 256               // N per pair (B split: 128 rows per CTA)
#define BNH 128
#define BKE 64               // K elements per stage (64 fp16 = 128 bytes/row)
#define NK (DIMK / BKE)                       // 112
#define NSTAGE 4
#define A_OFF 0
#define BP_OFF (BM * BKE * 2)                 // 16384
#define BG_OFF (BP_OFF + BNH * BKE * 2)       // 32768
#define STAGE_BYTES (BG_OFF + BNH * BKE * 2)  // 49152 per CTA
#define TX_TOTAL (2 * STAGE_BYTES)            // 98304
#define SMEM_DYN (NSTAGE * STAGE_BYTES + 1024) // 197632

// idesc cg2 kind::f16: dtype=F32(1), atype=btype=F16(0), N=256, M=256
#define IDESC ((1u << 4) | ((BN / 8) << 17) | ((256 / 16) << 24))

#if defined(__CUDA_ARCH_FEAT_SM103_ALL) || defined(__CUDA_ARCH_FEAT_SM100_ALL) || \
    (defined(__CUDA_ARCH_SPECIFIC__) && (__CUDA_ARCH_SPECIFIC__ >= 1000))
#define HAS_TCGEN05 1
#else
#define HAS_TCGEN05 0
#endif

__device__ float  g_kv_pre[(size_t)NCMP * ED];
__device__ __half g_x_h[(size_t)T_TOK * DIMK];      // 117 MB
__device__ __half g_wkv_h[(size_t)ED * DIMK];       // 29.4 MB
__device__ __half g_wgate_h[(size_t)ED * DIMK];     // 29.4 MB

// ---------------------------------------------------------------------------
__device__ __forceinline__ uint32_t smem_u32(const void* p) {
    return (uint32_t)__cvta_generic_to_shared(p);
}
__device__ __forceinline__ uint32_t ctarank() {
    uint32_t r; asm("mov.u32 %0, %%cluster_ctarank;" : "=r"(r)); return r;
}
__device__ __forceinline__ uint64_t make_desc(uint32_t addr) {
    const uint64_t base = (2ull << 61) | (1ull << 46) | (64ull << 32) | (1ull << 16);
    return base | ((uint64_t)(addr >> 4) & 0x3FFF);
}
__device__ __forceinline__ void mbar_init(uint32_t mbar, uint32_t count) {
    asm volatile("mbarrier.init.shared.b64 [%0], %1;" :: "r"(mbar), "r"(count) : "memory");
}
__device__ __forceinline__ void mbar_expect_tx(uint32_t mbar, uint32_t bytes) {
    asm volatile("mbarrier.arrive.expect_tx.shared.b64 _, [%0], %1;"
                 :: "r"(mbar), "r"(bytes) : "memory");
}
__device__ __forceinline__ void mbar_wait(uint32_t mbar, uint32_t parity) {
    asm volatile(
        "{\n\t.reg .pred P1;\n\t"
        "WAIT_%=:\n\t"
        "mbarrier.try_wait.parity.acquire.cta.shared::cta.b64 P1, [%0], %1, 0x989680;\n\t"
        "@P1 bra DONE_%=;\n\t"
        "bra WAIT_%=;\n\t"
        "DONE_%=:\n\t}"
        :: "r"(mbar), "r"(parity) : "memory");
}
__device__ __forceinline__ void mbar_inval(uint32_t mbar) {
    asm volatile("mbarrier.inval.shared.b64 [%0];" :: "r"(mbar) : "memory");
}
#define CLUSTER_SYNC() do { \
    asm volatile("barrier.cluster.arrive.aligned;" ::: "memory"); \
    asm volatile("barrier.cluster.wait.aligned;" ::: "memory"); \
} while (0)

#if HAS_TCGEN05
__device__ __forceinline__ void tma2d_cg2(uint32_t dst, const CUtensorMap* map,
                                          int cx, int cy, uint32_t mbar) {
    asm volatile(
        "{\n\t.reg .b32 lb;\n\t"
        "and.b32 lb, %4, 0xFEFFFFFF;\n\t"
        "cp.async.bulk.tensor.2d.cta_group::2.shared::cluster.global.tile."
        "mbarrier::complete_tx::bytes [%0], [%1, {%2, %3}], [lb];\n\t}"
        :: "r"(dst), "l"(map), "r"(cx), "r"(cy), "r"(mbar) : "memory");
}
__device__ __forceinline__ void mma_f16_cg2(uint32_t d_tmem, uint64_t a_desc,
                                            uint64_t b_desc, uint32_t idesc, uint32_t en) {
    asm volatile(
        "{\n\t.reg .pred p;\n\t"
        "setp.ne.u32 p, %5, 0;\n\t"
        "tcgen05.mma.cta_group::2.kind::f16 [%0], %1, %2, %3, "
        "{%4, %4, %4, %4, %4, %4, %4, %4}, p;\n\t}"
        :: "r"(d_tmem), "l"(a_desc), "l"(b_desc), "r"(idesc), "r"(0u), "r"(en)
        : "memory");
}
__device__ __forceinline__ void tcg_commit_mc(uint32_t mbar, uint16_t mask) {
    asm volatile(
        "tcgen05.commit.cta_group::2.mbarrier::arrive::one.shared::cluster."
        "multicast::cluster.b64 [%0], %1;"
        :: "r"(mbar), "h"(mask) : "memory");
}
#define TCG_ALLOC_CG2(sm_addr, n) \
    asm volatile("tcgen05.alloc.cta_group::2.sync.aligned.shared::cta.b32 [%0], %1;" \
                 :: "r"(sm_addr), "r"(n) : "memory")
#define TCG_DEALLOC_CG2(tmem, n) \
    asm volatile("tcgen05.dealloc.cta_group::2.sync.aligned.b32 %0, %1;" :: "r"(tmem), "r"(n))
#define TCG_RELINQ_CG2() \
    asm volatile("tcgen05.relinquish_alloc_permit.cta_group::2.sync.aligned;")
#define TCG_FENCE_AFTER()  asm volatile("tcgen05.fence::after_thread_sync;" ::: "memory")
#define TCG_WAIT_LD()      asm volatile("tcgen05.wait::ld.sync.aligned;" ::: "memory")

#define TCG_LD_X32(r, addr) \
    asm volatile( \
        "tcgen05.ld.sync.aligned.32x32b.x32.b32 " \
        "{%0, %1, %2, %3, %4, %5, %6, %7, " \
        " %8, %9, %10, %11, %12, %13, %14, %15, " \
        " %16, %17, %18, %19, %20, %21, %22, %23, " \
        " %24, %25, %26, %27, %28, %29, %30, %31}, [%32];" \
        : "=r"((r)[0]),  "=r"((r)[1]),  "=r"((r)[2]),  "=r"((r)[3]), \
          "=r"((r)[4]),  "=r"((r)[5]),  "=r"((r)[6]),  "=r"((r)[7]), \
          "=r"((r)[8]),  "=r"((r)[9]),  "=r"((r)[10]), "=r"((r)[11]), \
          "=r"((r)[12]), "=r"((r)[13]), "=r"((r)[14]), "=r"((r)[15]), \
          "=r"((r)[16]), "=r"((r)[17]), "=r"((r)[18]), "=r"((r)[19]), \
          "=r"((r)[20]), "=r"((r)[21]), "=r"((r)[22]), "=r"((r)[23]), \
          "=r"((r)[24]), "=r"((r)[25]), "=r"((r)[26]), "=r"((r)[27]), \
          "=r"((r)[28]), "=r"((r)[29]), "=r"((r)[30]), "=r"((r)[31]) \
        : "r"(addr))
#endif  // HAS_TCGEN05

// ---------------------------------------------------------------------------
// fp32 -> fp16 conversion (4 elements per thread)
// ---------------------------------------------------------------------------
__global__ __launch_bounds__(256) void cvt_f16_kernel(
    const float* __restrict__ src, __half* __restrict__ dst)
{
    const size_t i = (size_t)blockIdx.x * 256 + threadIdx.x;
    float4 v = reinterpret_cast<const float4*>(src)[i];
    __half2 lo = __floats2half2_rn(v.x, v.y);
    __half2 hi = __floats2half2_rn(v.z, v.w);
    reinterpret_cast<__half2*>(dst)[2 * i]     = lo;
    reinterpret_cast<__half2*>(dst)[2 * i + 1] = hi;
}

// ---------------------------------------------------------------------------
// 2CTA tcgen05 fp16 dual-GEMM, 4-stage pipeline with delayed refill
// ---------------------------------------------------------------------------
__global__ __launch_bounds__(256, 1) __cluster_dims__(2, 1, 1) void gemm_tc_kernel(
    const __grid_constant__ CUtensorMap tmx,
    const __grid_constant__ CUtensorMap tmk,
    const __grid_constant__ CUtensorMap tmg,
    const float* __restrict__ ape)
{
    extern __shared__ float dsm[];
    const int tid  = threadIdx.x;
    const uint32_t rank = ctarank();
    const int e0 = (blockIdx.x >> 1) * BN;
    const int t0 = blockIdx.y * 256 + rank * BM;
    const int eb = e0 + rank * BNH;

#if HAS_TCGEN05
    __shared__ uint32_t s_tmem;
    __shared__ __align__(8) uint64_t s_mbar[2 * NSTAGE];

    const int warp = tid >> 5;
    const int lane = tid & 31;
    const bool leader = (rank == 0);

    const uint32_t sb_raw = smem_u32(dsm);
    const uint32_t base   = (sb_raw + 1023u) & ~1023u;
    uint32_t mb_full[NSTAGE], mb_empty[NSTAGE];
#pragma unroll
    for (int s = 0; s < NSTAGE; s++) {
        mb_full[s]  = smem_u32(&s_mbar[s]);
        mb_empty[s] = smem_u32(&s_mbar[NSTAGE + s]);
    }

    if (warp == 0) TCG_ALLOC_CG2(smem_u32(&s_tmem), 512);
    if (tid == 0) {
#pragma unroll
        for (int s = 0; s < NSTAGE; s++) {
            mbar_init(mb_full[s], 1);
            mbar_init(mb_empty[s], 1);
        }
        if (leader) {
#pragma unroll
            for (int s = 0; s < NSTAGE; s++) mbar_expect_tx(mb_full[s], TX_TOTAL);
        }
    }
    __syncthreads();
    CLUSTER_SYNC();
    const uint32_t tmem = s_tmem;   // proj @ cols [0,256), gate @ cols [256,512)

    if (tid == 0) {
#pragma unroll
        for (int s = 0; s < NSTAGE; s++) {
            const uint32_t sa = base + s * STAGE_BYTES;
            tma2d_cg2(sa + A_OFF,  &tmx, s * BKE, t0, mb_full[s]);
            tma2d_cg2(sa + BP_OFF, &tmk, s * BKE, eb, mb_full[s]);
            tma2d_cg2(sa + BG_OFF, &tmg, s * BKE, eb, mb_full[s]);
        }
        int phf[NSTAGE] = {0, 0, 0, 0};
        int phe[NSTAGE] = {0, 0, 0, 0};
#pragma unroll 1
        for (int kt = 0; kt < NK; kt++) {
            const int s = kt & (NSTAGE - 1);
            if (leader) {
                mbar_wait(mb_full[s], phf[s]); phf[s] ^= 1;
                const uint32_t sa = base + s * STAGE_BYTES;
                const uint64_t ad  = make_desc(sa + A_OFF);
                const uint64_t bpd = make_desc(sa + BP_OFF);
                const uint64_t bgd = make_desc(sa + BG_OFF);
                const uint32_t en0 = (kt > 0);
#pragma unroll
                for (int ks = 0; ks < 4; ks++) {   // 4 × K=16 fp16 = 64
                    const uint32_t en = en0 | (uint32_t)(ks > 0);
                    mma_f16_cg2(tmem,      ad + 2 * ks, bpd + 2 * ks, IDESC, en);
                    mma_f16_cg2(tmem + BN, ad + 2 * ks, bgd + 2 * ks, IDESC, en);
                }
                if (kt + NSTAGE < NK) mbar_expect_tx(mb_full[s], TX_TOTAL);
                tcg_commit_mc(mb_empty[s], 0x3);
            }
            if (kt >= 1 && kt + NSTAGE - 1 < NK) {
                const int rs = (kt - 1) & (NSTAGE - 1);
                mbar_wait(mb_empty[rs], phe[rs]); phe[rs] ^= 1;
                const uint32_t sa = base + rs * STAGE_BYTES;
                const int k0 = (kt + NSTAGE - 1) * BKE;
                tma2d_cg2(sa + A_OFF,  &tmx, k0, t0, mb_full[rs]);
                tma2d_cg2(sa + BP_OFF, &tmk, k0, eb, mb_full[rs]);
                tma2d_cg2(sa + BG_OFF, &tmg, k0, eb, mb_full[rs]);
            }
        }
        const int ls = (NK - 1) & (NSTAGE - 1);
        mbar_wait(mb_empty[ls], phe[ls]);
    }
    __syncthreads();
    TCG_FENCE_AFTER();

    // ---- epilogue
    float* vt = (float*)((char*)dsm + (base - sb_raw));  // [32][257]
    if (warp < 4) {
#pragma unroll 1
        for (int cb = 0; cb < 8; cb++) {
            uint32_t pr[32], gr[32];
            TCG_LD_X32(pr, tmem + cb * 32);
            TCG_LD_X32(gr, tmem + BN + cb * 32);
            TCG_WAIT_LD();
            float v[32];
#pragma unroll
            for (int i = 0; i < 32; i++) {
                float p = __uint_as_float(pr[i]);
                float g = __uint_as_float(gr[i]);
                v[i] = p / (1.f + __expf(-g));
            }
#pragma unroll
            for (int i = 0; i < 32; i++) {
                v[i] += __shfl_xor_sync(0xffffffffu, v[i], 1);
                v[i] += __shfl_xor_sync(0xffffffffu, v[i], 2);
            }
            if ((lane & 3) == 0) {
                int row = warp * 8 + (lane >> 2);
#pragma unroll
                for (int i = 0; i < 32; i++) vt[row * 257 + cb * 32 + i] = v[i];
            }
        }
    }
    __syncthreads();

    {
        const int e = e0 + tid;
        const float asum = ape[e] + ape[ED + e] + ape[2 * ED + e] + ape[3 * ED + e];
        const int n0 = t0 >> 2;
#pragma unroll 4
        for (int row = 0; row < 32; row++) {
            float s = vt[row * 257 + tid];
            g_kv_pre[(size_t)(n0 + row) * ED + e] = 0.25f * (s + asum);
        }
    }
    __syncthreads();
    if (tid == 0) {
#pragma unroll
        for (int s = 0; s < NSTAGE; s++) { mbar_inval(mb_full[s]); mbar_inval(mb_empty[s]); }
    }
    __syncthreads();
    if (warp == 0) { TCG_RELINQ_CG2(); TCG_DEALLOC_CG2(tmem, 512); }
    CLUSTER_SYNC();

#else  // ---- generic-PTX fallback (correct, never executed on GB300) ----
    const int n0 = t0 >> 2;
    for (int idx = tid; idx < 32 * BN; idx += 256) {
        int row = idx / BN, col = idx % BN;
        int e = e0 + col;
        float acc = 0.f;
        for (int r = 0; r < 4; r++) {
            const __half* xr = g_x_h + (size_t)(t0 + row * 4 + r) * DIMK;
            const __half* wk = g_wkv_h + (size_t)e * DIMK;
            const __half* wg = g_wgate_h + (size_t)e * DIMK;
            float p = 0.f, g = 0.f;
            for (int k = 0; k < DIMK; k++) {
                p += __half2float(xr[k]) * __half2float(wk[k]);
                g += __half2float(xr[k]) * __half2float(wg[k]);
            }
            acc += p / (1.f + __expf(-g));
        }
        float asum = ape[e] + ape[ED + e] + ape[2 * ED + e] + ape[3 * ED + e];
        g_kv_pre[(size_t)(n0 + row) * ED + e] = 0.25f * (acc + asum);
    }
    (void)dsm;
#endif
}

// ---------------------------------------------------------------------------
// RMS-norm (per 512) + partial RoPE + scatter
// ---------------------------------------------------------------------------
__global__ __launch_bounds__(256) void norm_rope_scatter_kernel(
    const float* __restrict__ norm_weight, const float* __restrict__ rope_cos,
    const float* __restrict__ rope_sin, const int* __restrict__ slot_mapping,
    float* __restrict__ out)
{
    __shared__ float vals[ED];
    __shared__ float wsum[8];
    const int n = blockIdx.x;
    const int tid = threadIdx.x;

    float4 v = reinterpret_cast<const float4*>(g_kv_pre)[(size_t)n * 256 + tid];
    float ssq = v.x * v.x + v.y * v.y + v.z * v.z + v.w * v.w;
#pragma unroll
    for (int off = 16; off > 0; off >>= 1)
        ssq += __shfl_xor_sync(0xffffffffu, ssq, off);
    if ((tid & 31) == 0) wsum[tid >> 5] = ssq;
    __syncthreads();

    const int c = tid >> 7;
    float tot = wsum[c * 4] + wsum[c * 4 + 1] + wsum[c * 4 + 2] + wsum[c * 4 + 3];
    float scale = rsqrtf(tot * (1.0f / HEAD_DIM_) + EPS_);
    float4 nw = reinterpret_cast<const float4*>(norm_weight)[tid & 127];
    v.x *= scale * nw.x; v.y *= scale * nw.y; v.z *= scale * nw.z; v.w *= scale * nw.w;
    reinterpret_cast<float4*>(vals)[tid] = v;
    __syncthreads();

    const int din = tid & 127;
    if (din >= 112) {
        int rd = (din - 112) * 4;
        const float* cb = rope_cos + (size_t)n * ROPE_DIM_;
        const float* sb = rope_sin + (size_t)n * ROPE_DIM_;
        float vv[4] = {v.x, v.y, v.z, v.w};
#pragma unroll
        for (int j = 0; j < 4; j++) {
            int rdj = rd + j;
            float partner = (rdj < 32)
                ? -vals[c * HEAD_DIM_ + NOPE_DIM_ + rdj + 32]
                :  vals[c * HEAD_DIM_ + NOPE_DIM_ + rdj - 32];
            vv[j] = vv[j] * cb[rdj] + partner * sb[rdj];
        }
        v.x = vv[0]; v.y = vv[1]; v.z = vv[2]; v.w = vv[3];
    }

    const int slot = slot_mapping[n];
    reinterpret_cast<float4*>(out)[(size_t)slot * 256 + tid] = v;
}

// ---------------------------------------------------------------------------
// host side
// ---------------------------------------------------------------------------
typedef CUresult (*PFN_encodeTiled)(
    CUtensorMap*, CUtensorMapDataType, cuuint32_t, void*,
    const cuuint64_t*, const cuuint64_t*, const cuuint32_t*, const cuuint32_t*,
    CUtensorMapInterleave, CUtensorMapSwizzle, CUtensorMapL2promotion,
    CUtensorMapFloatOOBfill);

static void encode_map_f16(PFN_encodeTiled fn, CUtensorMap* tm, void* p,
                           uint64_t d0, uint64_t d1, uint32_t b0, uint32_t b1) {
    cuuint64_t dims[2]    = {d0, d1};
    cuuint64_t strides[1] = {d0 * 2};
    cuuint32_t box[2]     = {b0, b1};
    cuuint32_t estr[2]    = {1, 1};
    fn(tm, CU_TENSOR_MAP_DATA_TYPE_FLOAT16, 2, p, dims, strides, box, estr,
       CU_TENSOR_MAP_INTERLEAVE_NONE, CU_TENSOR_MAP_SWIZZLE_128B,
       CU_TENSOR_MAP_L2_PROMOTION_L2_128B, CU_TENSOR_MAP_FLOAT_OOB_FILL_NONE);
}

extern "C" void kernel_launch(void* const* d_in, const int* in_sizes, int n_in,
                              void* d_out, int out_size) {
    const float* x     = (const float*)d_in[0];
    const float* wkv   = (const float*)d_in[1];
    const float* wgate = (const float*)d_in[2];
    const float* ape   = (const float*)d_in[3];
    const float* nw    = (const float*)d_in[4];
    const float* rcos  = (const float*)d_in[5];
    const float* rsin  = (const float*)d_in[6];
    const float* cache = (const float*)d_in[7];
    const int*   slots = (const int*)d_in[8];
    float* out = (float*)d_out;

    void* fptr = nullptr;
    cudaDriverEntryPointQueryResult qr;
    cudaGetDriverEntryPointByVersion("cuTensorMapEncodeTiled", &fptr, 12000,
                                     cudaEnableDefault, &qr);
    PFN_encodeTiled enc = (PFN_encodeTiled)fptr;

    void *xh = nullptr, *wkh = nullptr, *wgh = nullptr;
    cudaGetSymbolAddress(&xh,  g_x_h);
    cudaGetSymbolAddress(&wkh, g_wkv_h);
    cudaGetSymbolAddress(&wgh, g_wgate_h);

    CUtensorMap tmx, tmk, tmg;
    encode_map_f16(enc, &tmx, xh,  DIMK, T_TOK, BKE, BM);
    encode_map_f16(enc, &tmk, wkh, DIMK, ED,    BKE, BNH);
    encode_map_f16(enc, &tmg, wgh, DIMK, ED,    BKE, BNH);

    cudaFuncSetAttribute(gemm_tc_kernel,
                         cudaFuncAttributeMaxDynamicSharedMemorySize, SMEM_DYN);

    // fork the big cache copy onto a side stream (shares DRAM, but free to try)
    static cudaStream_t s_copy = nullptr;
    static cudaEvent_t ev_fork = nullptr, ev_join = nullptr;
    if (s_copy == nullptr) {
        cudaStreamCreateWithFlags(&s_copy, cudaStreamNonBlocking);
        cudaEventCreateWithFlags(&ev_fork, cudaEventDisableTiming);
        cudaEventCreateWithFlags(&ev_join, cudaEventDisableTiming);
    }
    cudaEventRecord(ev_fork, 0);
    cudaStreamWaitEvent(s_copy, ev_fork, 0);
    cudaMemcpyAsync(out, cache, (size_t)NUM_SLOTS_ * ED * sizeof(float),
                    cudaMemcpyDeviceToDevice, s_copy);
    cudaEventRecord(ev_join, s_copy);

    // fp32 -> fp16 conversions (x, wkv, wgate)
    cvt_f16_kernel<<<(T_TOK * DIMK / 4) / 256, 256>>>(x,     (__half*)xh);
    cvt_f16_kernel<<<((size_t)ED * DIMK / 4) / 256, 256>>>(wkv,   (__half*)wkh);
    cvt_f16_kernel<<<((size_t)ED * DIMK / 4) / 256, 256>>>(wgate, (__half*)wgh);

    dim3 grid(2 * (ED / BN), T_TOK / 256);  // (8, 32), cluster (2,1,1) along x
    gemm_tc_kernel<<<grid, 256, SMEM_DYN>>>(tmx, tmk, tmg, ape);

    cudaStreamWaitEvent(0, ev_join, 0);  // copy must land before scatter
    norm_rope_scatter_kernel<<<NCMP, 256>>>(nw, rcos, rsin, slots, out);
}

// round 10
// speedup vs baseline: 1.6868x; 1.0229x over previous
#include <cuda_runtime.h>
#include <cuda.h>
#include <cuda_fp16.h>
#include <cstdint>

#define T_TOK 8192
#define DIMK 7168
#define ED 1024
#define NCMP 2048
#define HEAD_DIM_ 512
#define ROPE_DIM_ 64
#define NOPE_DIM_ 448
#define NUM_SLOTS_ 65536
#define EPS_ 1e-6f

// GEMM: cta_group::2, M=256/pair, N=256, fp16; persistent 64 clusters x 2 jobs
#define BM 128
#define BN 256
#define BNH 128
#define BKE 64               // 64 fp16 = 128 bytes/row
#define NK (DIMK / BKE)                       // 112
#define GTOT (2 * NK)                         // 224 global k-iterations
#define NSTAGE 4
#define A_OFF 0
#define BP_OFF (BM * BKE * 2)                 // 16384
#define BG_OFF (BP_OFF + BNH * BKE * 2)       // 32768
#define STAGE_BYTES (BG_OFF + BNH * BKE * 2)  // 49152
#define TX_TOTAL (2 * STAGE_BYTES)            // 98304
#define ASUM_OFF (NSTAGE * STAGE_BYTES)       // 196608 (256 floats after stages)
#define SMEM_DYN (NSTAGE * STAGE_BYTES + 2048) // 198656

// idesc cg2 kind::f16: dtype=F32(1), atype=btype=F16(0), N=256, M=256
#define IDESC ((1u << 4) | ((BN / 8) << 17) | ((256 / 16) << 24))

#if defined(__CUDA_ARCH_FEAT_SM103_ALL) || defined(__CUDA_ARCH_FEAT_SM100_ALL) || \
    (defined(__CUDA_ARCH_SPECIFIC__) && (__CUDA_ARCH_SPECIFIC__ >= 1000))
#define HAS_TCGEN05 1
#else
#define HAS_TCGEN05 0
#endif

__device__ float  g_kv_pre[(size_t)NCMP * ED];
__device__ __half g_x_h[(size_t)T_TOK * DIMK];
__device__ __half g_wkv_h[(size_t)ED * DIMK];
__device__ __half g_wgate_h[(size_t)ED * DIMK];

// ---------------------------------------------------------------------------
__device__ __forceinline__ uint32_t smem_u32(const void* p) {
    return (uint32_t)__cvta_generic_to_shared(p);
}
__device__ __forceinline__ uint32_t ctarank() {
    uint32_t r; asm("mov.u32 %0, %%cluster_ctarank;" : "=r"(r)); return r;
}
__device__ __forceinline__ uint64_t make_desc(uint32_t addr) {
    const uint64_t base = (2ull << 61) | (1ull << 46) | (64ull << 32) | (1ull << 16);
    return base | ((uint64_t)(addr >> 4) & 0x3FFF);
}
__device__ __forceinline__ void mbar_init(uint32_t mbar, uint32_t count) {
    asm volatile("mbarrier.init.shared.b64 [%0], %1;" :: "r"(mbar), "r"(count) : "memory");
}
__device__ __forceinline__ void mbar_expect_tx(uint32_t mbar, uint32_t bytes) {
    asm volatile("mbarrier.arrive.expect_tx.shared.b64 _, [%0], %1;"
                 :: "r"(mbar), "r"(bytes) : "memory");
}
__device__ __forceinline__ void mbar_wait(uint32_t mbar, uint32_t parity) {
    asm volatile(
        "{\n\t.reg .pred P1;\n\t"
        "WAIT_%=:\n\t"
        "mbarrier.try_wait.parity.acquire.cta.shared::cta.b64 P1, [%0], %1, 0x989680;\n\t"
        "@P1 bra DONE_%=;\n\t"
        "bra WAIT_%=;\n\t"
        "DONE_%=:\n\t}"
        :: "r"(mbar), "r"(parity) : "memory");
}
__device__ __forceinline__ void mbar_inval(uint32_t mbar) {
    asm volatile("mbarrier.inval.shared.b64 [%0];" :: "r"(mbar) : "memory");
}
#define CLUSTER_SYNC() do { \
    asm volatile("barrier.cluster.arrive.aligned;" ::: "memory"); \
    asm volatile("barrier.cluster.wait.aligned;" ::: "memory"); \
} while (0)

#if HAS_TCGEN05
__device__ __forceinline__ void tma2d_cg2(uint32_t dst, const CUtensorMap* map,
                                          int cx, int cy, uint32_t mbar) {
    asm volatile(
        "{\n\t.reg .b32 lb;\n\t"
        "and.b32 lb, %4, 0xFEFFFFFF;\n\t"
        "cp.async.bulk.tensor.2d.cta_group::2.shared::cluster.global.tile."
        "mbarrier::complete_tx::bytes [%0], [%1, {%2, %3}], [lb];\n\t}"
        :: "r"(dst), "l"(map), "r"(cx), "r"(cy), "r"(mbar) : "memory");
}
__device__ __forceinline__ void mma_f16_cg2(uint32_t d_tmem, uint64_t a_desc,
                                            uint64_t b_desc, uint32_t idesc, uint32_t en) {
    asm volatile(
        "{\n\t.reg .pred p;\n\t"
        "setp.ne.u32 p, %5, 0;\n\t"
        "tcgen05.mma.cta_group::2.kind::f16 [%0], %1, %2, %3, "
        "{%4, %4, %4, %4, %4, %4, %4, %4}, p;\n\t}"
        :: "r"(d_tmem), "l"(a_desc), "l"(b_desc), "r"(idesc), "r"(0u), "r"(en)
        : "memory");
}
__device__ __forceinline__ void tcg_commit_mc(uint32_t mbar, uint16_t mask) {
    asm volatile(
        "tcgen05.commit.cta_group::2.mbarrier::arrive::one.shared::cluster."
        "multicast::cluster.b64 [%0], %1;"
        :: "r"(mbar), "h"(mask) : "memory");
}
#define TCG_ALLOC_CG2(sm_addr, n) \
    asm volatile("tcgen05.alloc.cta_group::2.sync.aligned.shared::cta.b32 [%0], %1;" \
                 :: "r"(sm_addr), "r"(n) : "memory")
#define TCG_DEALLOC_CG2(tmem, n) \
    asm volatile("tcgen05.dealloc.cta_group::2.sync.aligned.b32 %0, %1;" :: "r"(tmem), "r"(n))
#define TCG_RELINQ_CG2() \
    asm volatile("tcgen05.relinquish_alloc_permit.cta_group::2.sync.aligned;")
#define TCG_FENCE_AFTER()  asm volatile("tcgen05.fence::after_thread_sync;" ::: "memory")
#define TCG_FENCE_BEFORE() asm volatile("tcgen05.fence::before_thread_sync;" ::: "memory")
#define TCG_WAIT_LD()      asm volatile("tcgen05.wait::ld.sync.aligned;" ::: "memory")

#define TCG_LD_X32(r, addr) \
    asm volatile( \
        "tcgen05.ld.sync.aligned.32x32b.x32.b32 " \
        "{%0, %1, %2, %3, %4, %5, %6, %7, " \
        " %8, %9, %10, %11, %12, %13, %14, %15, " \
        " %16, %17, %18, %19, %20, %21, %22, %23, " \
        " %24, %25, %26, %27, %28, %29, %30, %31}, [%32];" \
        : "=r"((r)[0]),  "=r"((r)[1]),  "=r"((r)[2]),  "=r"((r)[3]), \
          "=r"((r)[4]),  "=r"((r)[5]),  "=r"((r)[6]),  "=r"((r)[7]), \
          "=r"((r)[8]),  "=r"((r)[9]),  "=r"((r)[10]), "=r"((r)[11]), \
          "=r"((r)[12]), "=r"((r)[13]), "=r"((r)[14]), "=r"((r)[15]), \
          "=r"((r)[16]), "=r"((r)[17]), "=r"((r)[18]), "=r"((r)[19]), \
          "=r"((r)[20]), "=r"((r)[21]), "=r"((r)[22]), "=r"((r)[23]), \
          "=r"((r)[24]), "=r"((r)[25]), "=r"((r)[26]), "=r"((r)[27]), \
          "=r"((r)[28]), "=r"((r)[29]), "=r"((r)[30]), "=r"((r)[31]) \
        : "r"(addr))
#endif  // HAS_TCGEN05

// ---------------------------------------------------------------------------
__global__ __launch_bounds__(256) void cvt_f16_kernel(
    const float* __restrict__ src, __half* __restrict__ dst)
{
    const size_t i = (size_t)blockIdx.x * 256 + threadIdx.x;
    float4 v = reinterpret_cast<const float4*>(src)[i];
    __half2 lo = __floats2half2_rn(v.x, v.y);
    __half2 hi = __floats2half2_rn(v.z, v.w);
    reinterpret_cast<__half2*>(dst)[2 * i]     = lo;
    reinterpret_cast<__half2*>(dst)[2 * i + 1] = hi;
}

// ---------------------------------------------------------------------------
// persistent 2CTA tcgen05 fp16 dual-GEMM: 64 clusters x 2 jobs, flattened
// K pipeline prefetches across the job boundary; epilogue writes registers
// straight to g_kv_pre (stage SMEM stays live for job 2's TMA refills).
// ---------------------------------------------------------------------------
__global__ __launch_bounds__(256, 1) __cluster_dims__(2, 1, 1) void gemm_tc_kernel(
    const __grid_constant__ CUtensorMap tmx,
    const __grid_constant__ CUtensorMap tmk,
    const __grid_constant__ CUtensorMap tmg,
    const float* __restrict__ ape)
{
    extern __shared__ float dsm[];
    const int tid  = threadIdx.x;
    const uint32_t rank = ctarank();
    const int cl = blockIdx.x >> 1;            // cluster id 0..63
    const int e0 = (cl & 3) * BN;              // N-tile: invariant across jobs
    const int eb = e0 + rank * BNH;

#if HAS_TCGEN05
    __shared__ uint32_t s_tmem;
    __shared__ __align__(8) uint64_t s_mbar[2 * NSTAGE + 1];  // full[4], empty[4], done

    const int warp = tid >> 5;
    const int lane = tid & 31;
    const bool leader = (rank == 0);

    const uint32_t sb_raw = smem_u32(dsm);
    const uint32_t base   = (sb_raw + 1023u) & ~1023u;
    float* s_asum = (float*)((char*)dsm + (base - sb_raw) + ASUM_OFF);
    uint32_t mb_full[NSTAGE], mb_empty[NSTAGE];
#pragma unroll
    for (int s = 0; s < NSTAGE; s++) {
        mb_full[s]  = smem_u32(&s_mbar[s]);
        mb_empty[s] = smem_u32(&s_mbar[NSTAGE + s]);
    }
    const uint32_t mb_done = smem_u32(&s_mbar[2 * NSTAGE]);

    if (warp == 0) TCG_ALLOC_CG2(smem_u32(&s_tmem), 512);
    // per-cluster APE column sums (e0 fixed for both jobs)
    {
        const int e = e0 + tid;
        s_asum[tid] = ape[e] + ape[ED + e] + ape[2 * ED + e] + ape[3 * ED + e];
    }
    if (tid == 0) {
#pragma unroll
        for (int s = 0; s < NSTAGE; s++) {
            mbar_init(mb_full[s], 1);
            mbar_init(mb_empty[s], 1);
        }
        mbar_init(mb_done, 1);
        if (leader) {
#pragma unroll
            for (int s = 0; s < NSTAGE; s++) mbar_expect_tx(mb_full[s], TX_TOTAL);
        }
    }
    __syncthreads();
    CLUSTER_SYNC();
    const uint32_t tmem = s_tmem;   // proj @ cols [0,256), gate @ cols [256,512)

    // tile coords for global k-iteration g in [0, 2*NK)
    auto tile_cx = [&](int g) { return (g >= NK ? g - NK : g) * BKE; };
    auto tile_ty = [&](int g) {
        int job = cl + (g >= NK ? 64 : 0);
        return (job >> 2) * 256 + (int)rank * BM;
    };

    if (tid == 0) {
        // prefetch tiles 0..3 (job 0)
#pragma unroll
        for (int s = 0; s < NSTAGE; s++) {
            const uint32_t sa = base + s * STAGE_BYTES;
            tma2d_cg2(sa + A_OFF,  &tmx, tile_cx(s), tile_ty(s), mb_full[s]);
            tma2d_cg2(sa + BP_OFF, &tmk, tile_cx(s), eb, mb_full[s]);
            tma2d_cg2(sa + BG_OFF, &tmg, tile_cx(s), eb, mb_full[s]);
        }
    }

    int phf[NSTAGE] = {0, 0, 0, 0};
    int phe[NSTAGE] = {0, 0, 0, 0};

#pragma unroll 1
    for (int j = 0; j < 2; j++) {
        if (tid == 0) {
#pragma unroll 1
            for (int kt = 0; kt < NK; kt++) {
                const int g = j * NK + kt;
                const int s = g & (NSTAGE - 1);
                if (leader) {
                    mbar_wait(mb_full[s], phf[s]); phf[s] ^= 1;
                    const uint32_t sa = base + s * STAGE_BYTES;
                    const uint64_t ad  = make_desc(sa + A_OFF);
                    const uint64_t bpd = make_desc(sa + BP_OFF);
                    const uint64_t bgd = make_desc(sa + BG_OFF);
                    const uint32_t en0 = (kt > 0);
#pragma unroll
                    for (int ks = 0; ks < 4; ks++) {
                        const uint32_t en = en0 | (uint32_t)(ks > 0);
                        mma_f16_cg2(tmem,      ad + 2 * ks, bpd + 2 * ks, IDESC, en);
                        mma_f16_cg2(tmem + BN, ad + 2 * ks, bgd + 2 * ks, IDESC, en);
                    }
                    if (g + NSTAGE < GTOT) mbar_expect_tx(mb_full[s], TX_TOTAL);
                    tcg_commit_mc(mb_empty[s], 0x3);
                }
                // delayed refill: stage committed LAST iteration gets tile g+3
                if (g >= 1 && g + NSTAGE - 1 < GTOT) {
                    const int rs = (g - 1) & (NSTAGE - 1);
                    mbar_wait(mb_empty[rs], phe[rs]); phe[rs] ^= 1;
                    const uint32_t sa = base + rs * STAGE_BYTES;
                    const int gt = g + NSTAGE - 1;
                    tma2d_cg2(sa + A_OFF,  &tmx, tile_cx(gt), tile_ty(gt), mb_full[rs]);
                    tma2d_cg2(sa + BP_OFF, &tmk, tile_cx(gt), eb, mb_full[rs]);
                    tma2d_cg2(sa + BG_OFF, &tmg, tile_cx(gt), eb, mb_full[rs]);
                }
            }
            // job-completion signal: extra commit tracks ALL prior MMAs
            if (leader) tcg_commit_mc(mb_done, 0x3);
            mbar_wait(mb_done, j);
        }
        __syncthreads();
        TCG_FENCE_AFTER();

        // ---- epilogue for job j: registers -> g_kv_pre directly
        const int t0j = ((cl + (j ? 64 : 0)) >> 2) * 256 + (int)rank * BM;
        const int n0  = t0j >> 2;
        if (warp < 4) {
#pragma unroll 1
            for (int cb = 0; cb < 8; cb++) {
                uint32_t pr[32], gr[32];
                TCG_LD_X32(pr, tmem + cb * 32);
                TCG_LD_X32(gr, tmem + BN + cb * 32);
                TCG_WAIT_LD();
                float v[32];
#pragma unroll
                for (int i = 0; i < 32; i++) {
                    float p = __uint_as_float(pr[i]);
                    float gg = __uint_as_float(gr[i]);
                    v[i] = p / (1.f + __expf(-gg));
                }
#pragma unroll
                for (int i = 0; i < 32; i++) {
                    v[i] += __shfl_xor_sync(0xffffffffu, v[i], 1);
                    v[i] += __shfl_xor_sync(0xffffffffu, v[i], 2);
                }
                if ((lane & 3) == 0) {
                    const int row = warp * 8 + (lane >> 2);
                    float* dst = g_kv_pre + (size_t)(n0 + row) * ED + e0 + cb * 32;
                    const float* as = s_asum + cb * 32;
#pragma unroll
                    for (int q = 0; q < 8; q++) {
                        float4 o;
                        o.x = 0.25f * (v[4 * q]     + as[4 * q]);
                        o.y = 0.25f * (v[4 * q + 1] + as[4 * q + 1]);
                        o.z = 0.25f * (v[4 * q + 2] + as[4 * q + 2]);
                        o.w = 0.25f * (v[4 * q + 3] + as[4 * q + 3]);
                        reinterpret_cast<float4*>(dst)[q] = o;
                    }
                }
            }
            TCG_FENCE_BEFORE();
        }
        __syncthreads();   // all TMEM reads done before job 2's MMAs
    }

    __syncthreads();
    if (tid == 0) {
#pragma unroll
        for (int s = 0; s < NSTAGE; s++) { mbar_inval(mb_full[s]); mbar_inval(mb_empty[s]); }
        mbar_inval(mb_done);
    }
    __syncthreads();
    if (warp == 0) { TCG_RELINQ_CG2(); TCG_DEALLOC_CG2(tmem, 512); }
    CLUSTER_SYNC();

#else  // ---- generic-PTX fallback (correct, never executed on GB300) ----
    for (int j = 0; j < 2; j++) {
        const int job = cl + (j ? 64 : 0);
        const int t0j = (job >> 2) * 256 + (int)rank * BM;
        const int n0 = t0j >> 2;
        for (int idx = tid; idx < 32 * BN; idx += 256) {
            int row = idx / BN, col = idx % BN;
            int e = e0 + col;
            float acc = 0.f;
            for (int r = 0; r < 4; r++) {
                const __half* xr = g_x_h + (size_t)(t0j + row * 4 + r) * DIMK;
                const __half* wk = g_wkv_h + (size_t)e * DIMK;
                const __half* wg = g_wgate_h + (size_t)e * DIMK;
                float p = 0.f, g = 0.f;
                for (int k = 0; k < DIMK; k++) {
                    p += __half2float(xr[k]) * __half2float(wk[k]);
                    g += __half2float(xr[k]) * __half2float(wg[k]);
                }
                acc += p / (1.f + __expf(-g));
            }
            float asum = ape[e] + ape[ED + e] + ape[2 * ED + e] + ape[3 * ED + e];
            g_kv_pre[(size_t)(n0 + row) * ED + e] = 0.25f * (acc + asum);
        }
    }
    (void)dsm;
#endif
}

// ---------------------------------------------------------------------------
// RMS-norm (per 512) + partial RoPE + scatter
// ---------------------------------------------------------------------------
__global__ __launch_bounds__(256) void norm_rope_scatter_kernel(
    const float* __restrict__ norm_weight, const float* __restrict__ rope_cos,
    const float* __restrict__ rope_sin, const int* __restrict__ slot_mapping,
    float* __restrict__ out)
{
    __shared__ float vals[ED];
    __shared__ float wsum[8];
    const int n = blockIdx.x;
    const int tid = threadIdx.x;

    float4 v = reinterpret_cast<const float4*>(g_kv_pre)[(size_t)n * 256 + tid];
    float ssq = v.x * v.x + v.y * v.y + v.z * v.z + v.w * v.w;
#pragma unroll
    for (int off = 16; off > 0; off >>= 1)
        ssq += __shfl_xor_sync(0xffffffffu, ssq, off);
    if ((tid & 31) == 0) wsum[tid >> 5] = ssq;
    __syncthreads();

    const int c = tid >> 7;
    float tot = wsum[c * 4] + wsum[c * 4 + 1] + wsum[c * 4 + 2] + wsum[c * 4 + 3];
    float scale = rsqrtf(tot * (1.0f / HEAD_DIM_) + EPS_);
    float4 nw = reinterpret_cast<const float4*>(norm_weight)[tid & 127];
    v.x *= scale * nw.x; v.y *= scale * nw.y; v.z *= scale * nw.z; v.w *= scale * nw.w;
    reinterpret_cast<float4*>(vals)[tid] = v;
    __syncthreads();

    const int din = tid & 127;
    if (din >= 112) {
        int rd = (din - 112) * 4;
        const float* cb = rope_cos + (size_t)n * ROPE_DIM_;
        const float* sb = rope_sin + (size_t)n * ROPE_DIM_;
        float vv[4] = {v.x, v.y, v.z, v.w};
#pragma unroll
        for (int j = 0; j < 4; j++) {
            int rdj = rd + j;
            float partner = (rdj < 32)
                ? -vals[c * HEAD_DIM_ + NOPE_DIM_ + rdj + 32]
                :  vals[c * HEAD_DIM_ + NOPE_DIM_ + rdj - 32];
            vv[j] = vv[j] * cb[rdj] + partner * sb[rdj];
        }
        v.x = vv[0]; v.y = vv[1]; v.z = vv[2]; v.w = vv[3];
    }

    const int slot = slot_mapping[n];
    reinterpret_cast<float4*>(out)[(size_t)slot * 256 + tid] = v;
}

// ---------------------------------------------------------------------------
// host side
// ---------------------------------------------------------------------------
typedef CUresult (*PFN_encodeTiled)(
    CUtensorMap*, CUtensorMapDataType, cuuint32_t, void*,
    const cuuint64_t*, const cuuint64_t*, const cuuint32_t*, const cuuint32_t*,
    CUtensorMapInterleave, CUtensorMapSwizzle, CUtensorMapL2promotion,
    CUtensorMapFloatOOBfill);

static void encode_map_f16(PFN_encodeTiled fn, CUtensorMap* tm, void* p,
                           uint64_t d0, uint64_t d1, uint32_t b0, uint32_t b1) {
    cuuint64_t dims[2]    = {d0, d1};
    cuuint64_t strides[1] = {d0 * 2};
    cuuint32_t box[2]     = {b0, b1};
    cuuint32_t estr[2]    = {1, 1};
    fn(tm, CU_TENSOR_MAP_DATA_TYPE_FLOAT16, 2, p, dims, strides, box, estr,
       CU_TENSOR_MAP_INTERLEAVE_NONE, CU_TENSOR_MAP_SWIZZLE_128B,
       CU_TENSOR_MAP_L2_PROMOTION_L2_128B, CU_TENSOR_MAP_FLOAT_OOB_FILL_NONE);
}

extern "C" void kernel_launch(void* const* d_in, const int* in_sizes, int n_in,
                              void* d_out, int out_size) {
    const float* x     = (const float*)d_in[0];
    const float* wkv   = (const float*)d_in[1];
    const float* wgate = (const float*)d_in[2];
    const float* ape   = (const float*)d_in[3];
    const float* nw    = (const float*)d_in[4];
    const float* rcos  = (const float*)d_in[5];
    const float* rsin  = (const float*)d_in[6];
    const float* cache = (const float*)d_in[7];
    const int*   slots = (const int*)d_in[8];
    float* out = (float*)d_out;

    void* fptr = nullptr;
    cudaDriverEntryPointQueryResult qr;
    cudaGetDriverEntryPointByVersion("cuTensorMapEncodeTiled", &fptr, 12000,
                                     cudaEnableDefault, &qr);
    PFN_encodeTiled enc = (PFN_encodeTiled)fptr;

    void *xh = nullptr, *wkh = nullptr, *wgh = nullptr;
    cudaGetSymbolAddress(&xh,  g_x_h);
    cudaGetSymbolAddress(&wkh, g_wkv_h);
    cudaGetSymbolAddress(&wgh, g_wgate_h);

    CUtensorMap tmx, tmk, tmg;
    encode_map_f16(enc, &tmx, xh,  DIMK, T_TOK, BKE, BM);
    encode_map_f16(enc, &tmk, wkh, DIMK, ED,    BKE, BNH);
    encode_map_f16(enc, &tmg, wgh, DIMK, ED,    BKE, BNH);

    cudaFuncSetAttribute(gemm_tc_kernel,
                         cudaFuncAttributeMaxDynamicSharedMemorySize, SMEM_DYN);

    // memcpy-ONLY side stream (proven zero-alloc); all kernels on stream 0
    static cudaStream_t s_copy = nullptr;
    static cudaEvent_t ev_fork = nullptr, ev_copy = nullptr;
    if (s_copy == nullptr) {
        cudaStreamCreateWithFlags(&s_copy, cudaStreamNonBlocking);
        cudaEventCreateWithFlags(&ev_fork, cudaEventDisableTiming);
        cudaEventCreateWithFlags(&ev_copy, cudaEventDisableTiming);
    }
    cudaEventRecord(ev_fork, 0);
    cudaStreamWaitEvent(s_copy, ev_fork, 0);
    cudaMemcpyAsync(out, cache, (size_t)NUM_SLOTS_ * ED * sizeof(float),
                    cudaMemcpyDeviceToDevice, s_copy);
    cudaEventRecord(ev_copy, s_copy);

    // conversions (default stream, serial — DRAM-bound)
    cvt_f16_kernel<<<((size_t)ED * DIMK / 4) / 256, 256>>>(wkv,   (__half*)wkh);
    cvt_f16_kernel<<<((size_t)ED * DIMK / 4) / 256, 256>>>(wgate, (__half*)wgh);
    cvt_f16_kernel<<<((size_t)T_TOK * DIMK / 4) / 256, 256>>>(x,  (__half*)xh);

    // persistent GEMM: 64 clusters x 2 jobs = 128 CTAs, single wave
    gemm_tc_kernel<<<dim3(128, 1, 1), 256, SMEM_DYN>>>(tmx, tmk, tmg, ape);

    cudaStreamWaitEvent(0, ev_copy, 0);
    norm_rope_scatter_kernel<<<NCMP, 256>>>(nw, rcos, rsin, slots, out);
}